// round 14
// baseline (speedup 1.0000x reference)
#include <cuda_runtime.h>
#include <cuda_bf16.h>
#include <cstdint>

#define NN 50000
#define NE 800000
#define MAXD 256
#define NBLK 196   // ceil(NN/256)

// ---------------- scratch (device globals) ----------------
__device__ int   g_deg_in[NN];
__device__ int   g_deg_out[NN];
__device__ int   g_cnt[NN];
__device__ float g_norm_s[NN];
__device__ float g_norm_d[NN];
__device__ int   g_off[NN + 1];
__device__ int   g_bsum[NBLK];
__device__ int   g_csr[NE];
__device__ float g_Y[(size_t)NN * MAXD];

// pre-split GEMM A operand (h * norm_s), bf16 hi/lo
__device__ __nv_bfloat16 g_Ah[(size_t)NN * 512];
__device__ __nv_bfloat16 g_Al[(size_t)NN * 512];

// pre-converted weights, transposed to [N][K], bf16 hi/lo split
#define WOFF0 0
#define WOFF1 131072
#define WOFF2 196608
#define WOFF3 229376
#define WTOT  237568
__device__ __nv_bfloat16 g_Bh[WTOT];
__device__ __nv_bfloat16 g_Bl[WTOT];

// ---------------- helpers ----------------
__device__ __forceinline__ uint32_t smem_to_u32(const void* p) {
    uint32_t a;
    asm("{ .reg .u64 t; cvta.to.shared.u64 t, %1; cvt.u32.u64 %0, t; }" : "=r"(a) : "l"(p));
    return a;
}
__device__ __forceinline__ void cp16(uint32_t dst, const void* src, int sz) {
    asm volatile("cp.async.cg.shared.global [%0], [%1], 16, %2;" :: "r"(dst), "l"(src), "r"(sz));
}
#define CP_COMMIT() asm volatile("cp.async.commit_group;" ::: "memory")
#define CP_WAIT(n)  asm volatile("cp.async.wait_group %0;" :: "n"(n) : "memory")

__device__ __forceinline__ void mma16816(float& c0, float& c1, float& c2, float& c3,
                                         uint32_t a0, uint32_t a1, uint32_t a2, uint32_t a3,
                                         uint32_t b0, uint32_t b1) {
    asm volatile(
        "mma.sync.aligned.m16n8k16.row.col.f32.bf16.bf16.f32 "
        "{%0,%1,%2,%3}, {%4,%5,%6,%7}, {%8,%9}, {%0,%1,%2,%3};"
        : "+f"(c0), "+f"(c1), "+f"(c2), "+f"(c3)
        : "r"(a0), "r"(a1), "r"(a2), "r"(a3), "r"(b0), "r"(b1));
}

__device__ __forceinline__ void ldsm4(uint32_t& r0, uint32_t& r1, uint32_t& r2, uint32_t& r3,
                                      uint32_t addr) {
    asm volatile("ldmatrix.sync.aligned.m8n8.x4.shared.b16 {%0,%1,%2,%3}, [%4];"
                 : "=r"(r0), "=r"(r1), "=r"(r2), "=r"(r3) : "r"(addr));
}

__device__ __forceinline__ void split2(float x0, float x1, uint32_t& hi, uint32_t& lo) {
    __nv_bfloat16 h0 = __float2bfloat16(x0), h1 = __float2bfloat16(x1);
    __nv_bfloat162 hp; hp.x = h0; hp.y = h1;
    __nv_bfloat162 lp = __floats2bfloat162_rn(x0 - __bfloat162float(h0),
                                              x1 - __bfloat162float(h1));
    hi = *reinterpret_cast<uint32_t*>(&hp);
    lo = *reinterpret_cast<uint32_t*>(&lp);
}

// ---------------- graph preprocessing ----------------
__global__ void k_zero() {
    int i = blockIdx.x * blockDim.x + threadIdx.x;
    if (i < NN) { g_deg_in[i] = 0; g_deg_out[i] = 0; g_cnt[i] = 0; }
}

__global__ void k_deg(const int* __restrict__ src, const int* __restrict__ dst) {
    int i = blockIdx.x * blockDim.x + threadIdx.x;
    if (i < NE) {
        atomicAdd(&g_deg_out[src[i]], 1);
        atomicAdd(&g_deg_in[dst[i]], 1);
    }
}

__global__ void k_norm() {
    int i = blockIdx.x * blockDim.x + threadIdx.x;
    if (i < NN) {
        int doo = g_deg_out[i]; if (doo < 1) doo = 1;
        int dii = g_deg_in[i];  if (dii < 1) dii = 1;
        g_norm_s[i] = rsqrtf((float)doo);
        g_norm_d[i] = rsqrtf((float)dii);
    }
}

__global__ __launch_bounds__(256) void k_scan1() {
    __shared__ int wsum[8];
    int i = blockIdx.x * 256 + threadIdx.x;
    int v = (i < NN) ? g_deg_in[i] : 0;
#pragma unroll
    for (int d = 16; d > 0; d >>= 1) v += __shfl_down_sync(0xffffffffu, v, d);
    int lane = threadIdx.x & 31, wid = threadIdx.x >> 5;
    if (lane == 0) wsum[wid] = v;
    __syncthreads();
    if (threadIdx.x < 8) {
        int s = wsum[threadIdx.x];
#pragma unroll
        for (int d = 4; d > 0; d >>= 1) s += __shfl_down_sync(0xffu, s, d);
        if (threadIdx.x == 0) g_bsum[blockIdx.x] = s;
    }
}

__global__ __launch_bounds__(256) void k_scan2() {
    __shared__ int wsc[8];
    int t = threadIdx.x;
    int v = (t < NBLK) ? g_bsum[t] : 0;
    int lane = t & 31, wid = t >> 5;
    int inc = v;
#pragma unroll
    for (int d = 1; d < 32; d <<= 1) {
        int u = __shfl_up_sync(0xffffffffu, inc, d);
        if (lane >= d) inc += u;
    }
    if (lane == 31) wsc[wid] = inc;
    __syncthreads();
    if (t < 8) {
        int s = wsc[t];
        int si = s;
#pragma unroll
        for (int d = 1; d < 8; d <<= 1) {
            int u = __shfl_up_sync(0xffu, si, d);
            if (t >= d) si += u;
        }
        wsc[t] = si - s;
        if (t == 7) g_off[NN] = si;
    }
    __syncthreads();
    int excl = inc - v + wsc[wid];
    if (t < NBLK) g_bsum[t] = excl;
}

__global__ __launch_bounds__(256) void k_scan3() {
    __shared__ int wsc[8];
    int i = blockIdx.x * 256 + threadIdx.x;
    int v = (i < NN) ? g_deg_in[i] : 0;
    int lane = threadIdx.x & 31, wid = threadIdx.x >> 5;
    int inc = v;
#pragma unroll
    for (int d = 1; d < 32; d <<= 1) {
        int u = __shfl_up_sync(0xffffffffu, inc, d);
        if (lane >= d) inc += u;
    }
    if (lane == 31) wsc[wid] = inc;
    __syncthreads();
    if (threadIdx.x < 8) {
        int s = wsc[threadIdx.x];
        int si = s;
#pragma unroll
        for (int d = 1; d < 8; d <<= 1) {
            int u = __shfl_up_sync(0xffu, si, d);
            if (threadIdx.x >= d) si += u;
        }
        wsc[threadIdx.x] = si - s;
    }
    __syncthreads();
    int excl = inc - v + wsc[wid] + g_bsum[blockIdx.x];
    if (i < NN) g_off[i] = excl;
}

__global__ void k_fill(const int* __restrict__ src, const int* __restrict__ dst) {
    int i = blockIdx.x * blockDim.x + threadIdx.x;
    if (i < NE) {
        int d = dst[i];
        int p = atomicAdd(&g_cnt[d], 1);
        g_csr[g_off[d] + p] = src[i];
    }
}

// ---------------- weight pre-conversion: W[K][N] fp32 -> Bh/Bl[N][K] bf16 ----------------
__global__ void k_wconv(const float* __restrict__ W, int K, int N, int outOff) {
    int idx = blockIdx.x * blockDim.x + threadIdx.x;
    if (idx >= K * N) return;
    int k = idx / N, n = idx % N;
    float x = W[idx];
    __nv_bfloat16 h = __float2bfloat16(x);
    float lo = x - __bfloat162float(h);
    g_Bh[outOff + n * K + k] = h;
    g_Bl[outOff + n * K + k] = __float2bfloat16(lo);
}

// ---------------- feature pre-split ----------------
__global__ __launch_bounds__(256) void k_sfeat(const float* __restrict__ feat) {
    int idx = blockIdx.x * 256 + threadIdx.x;
    if (idx >= NN * 128) return;
    int node = idx >> 7;
    float ns = g_norm_s[node];
    float4 a = ((const float4*)feat)[idx];
    uint32_t h0, l0, h1, l1;
    split2(a.x * ns, a.y * ns, h0, l0);
    split2(a.z * ns, a.w * ns, h1, l1);
    ((uint2*)g_Ah)[idx] = make_uint2(h0, h1);
    ((uint2*)g_Al)[idx] = make_uint2(l0, l1);
}

// ---------------- cp.async stage issue ----------------
template <int BN, int THREADS>
__device__ __forceinline__ void issue_stage(
    uint32_t sb,
    const __nv_bfloat16* __restrict__ Ah, const __nv_bfloat16* __restrict__ Al,
    const __nv_bfloat16* __restrict__ Bh, const __nv_bfloat16* __restrict__ Bl,
    int tid, int mTile, int nTile, int k0, int M, int K) {
    const int A_BYTES = 128 * 40 * 2;
    const int B_BYTES = BN * 40 * 2;
#pragma unroll
    for (int it = 0; it < 512 / THREADS; it++) {
        int c = tid + it * THREADS;
        int row = c >> 2, seg = c & 3;
        int gm = mTile + row;
        int sz = (gm < M) ? 16 : 0;
        int gms = (gm < M) ? gm : (M - 1);
        size_t goff = (size_t)gms * K + k0 + seg * 8;
        uint32_t d = sb + row * 80 + seg * 16;
        cp16(d, Ah + goff, sz);
        cp16(d + A_BYTES, Al + goff, sz);
    }
#pragma unroll
    for (int it = 0; it < (BN * 4) / THREADS; it++) {
        int c = tid + it * THREADS;
        int row = c >> 2, seg = c & 3;
        size_t goff = (size_t)(nTile + row) * K + k0 + seg * 8;
        uint32_t d = sb + 2 * A_BYTES + row * 80 + seg * 16;
        cp16(d, Bh + goff, 16);
        cp16(d + B_BYTES, Bl + goff, 16);
    }
}

// ---------------- pipelined tensor-core GEMM (3-term bf16 split, ldmatrix + A-prefetch) ----------------
template <int BN>
__global__ __launch_bounds__(2 * (BN / 32) * 32, 2)
void k_pgemm(const __nv_bfloat16* __restrict__ Ah, const __nv_bfloat16* __restrict__ Al,
             const __nv_bfloat16* __restrict__ Bh, const __nv_bfloat16* __restrict__ Bl,
             float* __restrict__ Y, int M, int K, int Nstride) {
    const int THREADS = 2 * (BN / 32) * 32;
    const int ST = 40;
    const int A_BYTES = 128 * ST * 2;
    const int B_BYTES = BN * ST * 2;
    const int STAGE = 2 * A_BYTES + 2 * B_BYTES;
    extern __shared__ char smem[];
    uint32_t sbase = smem_to_u32(smem);

    int tid = threadIdx.x;
    int wid = tid >> 5;
    int lane = tid & 31;
    int grp = lane >> 2;
    int qid = lane & 3;
    int mbase = (wid & 1) * 64;
    int nbase = (wid >> 1) * 32;
    int mTile = blockIdx.y * 128;
    int nTile = blockIdx.x * BN;
    int nchunk = K >> 5;

    // per-thread ldmatrix byte offsets
    uint32_t aoff = (uint32_t)(mbase + ((lane >> 3) & 1) * 8 + (lane & 7)) * 80
                  + ((lane >> 4) & 1) * 16;
    uint32_t boff = (uint32_t)(nbase + ((lane >> 4) & 1) * 8 + (lane & 7)) * 80
                  + ((lane >> 3) & 1) * 16;

    float acc[4][4][4];
#pragma unroll
    for (int i = 0; i < 4; i++)
#pragma unroll
        for (int j = 0; j < 4; j++)
#pragma unroll
            for (int r = 0; r < 4; r++) acc[i][j][r] = 0.f;

    issue_stage<BN, THREADS>(sbase, Ah, Al, Bh, Bl, tid, mTile, nTile, 0, M, K);
    CP_COMMIT();

    for (int c = 0; c < nchunk; c++) {
        if (c + 1 < nchunk) {
            issue_stage<BN, THREADS>(sbase + ((c + 1) & 1) * STAGE, Ah, Al, Bh, Bl,
                                     tid, mTile, nTile, (c + 1) * 32, M, K);
            CP_COMMIT();
            CP_WAIT(1);
        } else {
            CP_WAIT(0);
        }
        __syncthreads();

        uint32_t stA = sbase + (c & 1) * STAGE;           // A_hi
        uint32_t stB = stA + 2 * A_BYTES;                 // B_hi

#pragma unroll
        for (int ks = 0; ks < 2; ks++) {
            uint32_t kby = (uint32_t)(ks * 32);           // k16 step -> 32 bytes

            uint32_t bh[4][2], bl[4][2];
#pragma unroll
            for (int p = 0; p < 2; p++) {
                uint32_t ba = stB + boff + p * 16 * 80 + kby;
                ldsm4(bh[2 * p][0], bh[2 * p][1], bh[2 * p + 1][0], bh[2 * p + 1][1], ba);
                ldsm4(bl[2 * p][0], bl[2 * p][1], bl[2 * p + 1][0], bl[2 * p + 1][1],
                      ba + B_BYTES);
            }

            // A fragment software pipeline: prefetch mt+1 while mma on mt
            uint32_t ac[8], an[8];
            {
                uint32_t aa = stA + aoff + kby;
                ldsm4(ac[0], ac[1], ac[2], ac[3], aa);
                ldsm4(ac[4], ac[5], ac[6], ac[7], aa + A_BYTES);
            }
#pragma unroll
            for (int mt = 0; mt < 4; mt++) {
                if (mt < 3) {
                    uint32_t aa = stA + aoff + (mt + 1) * 16 * 80 + kby;
                    ldsm4(an[0], an[1], an[2], an[3], aa);
                    ldsm4(an[4], an[5], an[6], an[7], aa + A_BYTES);
                }
#pragma unroll
                for (int nt = 0; nt < 4; nt++) {
                    mma16816(acc[mt][nt][0], acc[mt][nt][1], acc[mt][nt][2], acc[mt][nt][3],
                             ac[0], ac[1], ac[2], ac[3], bh[nt][0], bh[nt][1]);
                    mma16816(acc[mt][nt][0], acc[mt][nt][1], acc[mt][nt][2], acc[mt][nt][3],
                             ac[0], ac[1], ac[2], ac[3], bl[nt][0], bl[nt][1]);
                    mma16816(acc[mt][nt][0], acc[mt][nt][1], acc[mt][nt][2], acc[mt][nt][3],
                             ac[4], ac[5], ac[6], ac[7], bh[nt][0], bh[nt][1]);
                }
                if (mt < 3) {
#pragma unroll
                    for (int r = 0; r < 8; r++) ac[r] = an[r];
                }
            }
        }
        __syncthreads();
    }

    // epilogue
#pragma unroll
    for (int mt = 0; mt < 4; mt++) {
        int r0 = mTile + mbase + mt * 16 + grp;
        int r1 = r0 + 8;
#pragma unroll
        for (int nt = 0; nt < 4; nt++) {
            int col = nTile + nbase + nt * 8 + qid * 2;
            if (r0 < M) {
                float2 v = make_float2(acc[mt][nt][0], acc[mt][nt][1]);
                *(float2*)(Y + (size_t)r0 * Nstride + col) = v;
            }
            if (r1 < M) {
                float2 v = make_float2(acc[mt][nt][2], acc[mt][nt][3]);
                *(float2*)(Y + (size_t)r1 * Nstride + col) = v;
            }
        }
    }
}

// ---------------- aggregation (4-edge unrolled; optionally emits split A operand) ----------------
template <int DIM, bool RELU, bool WF32, bool WSPLIT>
__global__ __launch_bounds__(256) void k_agg(const float* __restrict__ Y,
                                             const float* __restrict__ b,
                                             float* __restrict__ outF,
                                             __nv_bfloat16* __restrict__ outH,
                                             __nv_bfloat16* __restrict__ outL) {
    const int VPT = DIM / 4;
    const int G = 256 / VPT;
    int t = threadIdx.x;
    int node = blockIdx.x * G + t / VPT;
    int lane = t % VPT;
    if (node >= NN) return;

    int p0 = g_off[node];
    int p1 = g_off[node + 1];
    const float4* Yv = (const float4*)Y;

    float4 a0 = make_float4(0.f, 0.f, 0.f, 0.f);
    float4 a1 = make_float4(0.f, 0.f, 0.f, 0.f);
    float4 a2 = make_float4(0.f, 0.f, 0.f, 0.f);
    float4 a3 = make_float4(0.f, 0.f, 0.f, 0.f);
    int p = p0;
    for (; p + 3 < p1; p += 4) {
        int s0 = g_csr[p];
        int s1 = g_csr[p + 1];
        int s2 = g_csr[p + 2];
        int s3 = g_csr[p + 3];
        float4 v0 = __ldg(&Yv[(size_t)s0 * VPT + lane]);
        float4 v1 = __ldg(&Yv[(size_t)s1 * VPT + lane]);
        float4 v2 = __ldg(&Yv[(size_t)s2 * VPT + lane]);
        float4 v3 = __ldg(&Yv[(size_t)s3 * VPT + lane]);
        a0.x += v0.x; a0.y += v0.y; a0.z += v0.z; a0.w += v0.w;
        a1.x += v1.x; a1.y += v1.y; a1.z += v1.z; a1.w += v1.w;
        a2.x += v2.x; a2.y += v2.y; a2.z += v2.z; a2.w += v2.w;
        a3.x += v3.x; a3.y += v3.y; a3.z += v3.z; a3.w += v3.w;
    }
    for (; p < p1; p++) {
        int s0 = g_csr[p];
        float4 v0 = __ldg(&Yv[(size_t)s0 * VPT + lane]);
        a0.x += v0.x; a0.y += v0.y; a0.z += v0.z; a0.w += v0.w;
    }

    float nd = g_norm_d[node];
    float4 bb = ((const float4*)b)[lane];
    float4 r;
    r.x = (a0.x + a1.x + a2.x + a3.x) * nd + bb.x;
    r.y = (a0.y + a1.y + a2.y + a3.y) * nd + bb.y;
    r.z = (a0.z + a1.z + a2.z + a3.z) * nd + bb.z;
    r.w = (a0.w + a1.w + a2.w + a3.w) * nd + bb.w;
    if (RELU) {
        r.x = fmaxf(r.x, 0.f); r.y = fmaxf(r.y, 0.f);
        r.z = fmaxf(r.z, 0.f); r.w = fmaxf(r.w, 0.f);
    }
    size_t oidx = (size_t)node * VPT + lane;
    if (WF32) ((float4*)outF)[oidx] = r;
    if (WSPLIT) {
        float ns = g_norm_s[node];
        uint32_t h0, l0, h1, l1;
        split2(r.x * ns, r.y * ns, h0, l0);
        split2(r.z * ns, r.w * ns, h1, l1);
        ((uint2*)outH)[oidx] = make_uint2(h0, h1);
        ((uint2*)outL)[oidx] = make_uint2(l0, l1);
    }
}

// ---------------- launch ----------------
extern "C" void kernel_launch(void* const* d_in, const int* in_sizes, int n_in,
                              void* d_out, int out_size) {
    const float* feat = (const float*)d_in[0];
    const int*   src  = (const int*)d_in[1];
    const int*   dst  = (const int*)d_in[2];
    const float* W0 = (const float*)d_in[3];
    const float* b0 = (const float*)d_in[4];
    const float* W1 = (const float*)d_in[5];
    const float* b1 = (const float*)d_in[6];
    const float* W2 = (const float*)d_in[7];
    const float* b2 = (const float*)d_in[8];
    const float* W3 = (const float*)d_in[9];
    const float* b3 = (const float*)d_in[10];

    float* out    = (float*)d_out;
    float* aspect = out;                          // NN x 128
    float* final_ = out + (size_t)NN * 128;       // NN x 64

    void* p;
    cudaGetSymbolAddress(&p, g_Y);  float* Y = (float*)p;
    cudaGetSymbolAddress(&p, g_Ah); __nv_bfloat16* Ah = (__nv_bfloat16*)p;
    cudaGetSymbolAddress(&p, g_Al); __nv_bfloat16* Al = (__nv_bfloat16*)p;
    cudaGetSymbolAddress(&p, g_Bh); __nv_bfloat16* Bh = (__nv_bfloat16*)p;
    cudaGetSymbolAddress(&p, g_Bl); __nv_bfloat16* Bl = (__nv_bfloat16*)p;

    const int SM128 = 2 * (2 * 128 * 40 * 2 + 2 * 128 * 40 * 2);  // 81920
    const int SM64  = 2 * (2 * 128 * 40 * 2 + 2 * 64 * 40 * 2);   // 61440
    cudaFuncSetAttribute(k_pgemm<128>, cudaFuncAttributeMaxDynamicSharedMemorySize, SM128);
    cudaFuncSetAttribute(k_pgemm<64>,  cudaFuncAttributeMaxDynamicSharedMemorySize, SM64);

    const int TB = 256;
    int nodeBlocks = (NN + TB - 1) / TB;
    int edgeBlocks = (NE + TB - 1) / TB;
    int mTiles = (NN + 127) / 128;               // 391

    // preprocessing
    k_zero<<<nodeBlocks, TB>>>();
    k_deg<<<edgeBlocks, TB>>>(src, dst);
    k_norm<<<nodeBlocks, TB>>>();
    k_scan1<<<NBLK, TB>>>();
    k_scan2<<<1, TB>>>();
    k_scan3<<<NBLK, TB>>>();
    k_fill<<<edgeBlocks, TB>>>(src, dst);

    // weight conversion + feature split
    k_wconv<<<(512 * 256 + 255) / 256, 256>>>(W0, 512, 256, WOFF0);
    k_wconv<<<(256 * 256 + 255) / 256, 256>>>(W1, 256, 256, WOFF1);
    k_wconv<<<(256 * 128 + 255) / 256, 256>>>(W2, 256, 128, WOFF2);
    k_wconv<<<(128 * 64 + 255) / 256, 256>>>(W3, 128, 64, WOFF3);
    k_sfeat<<<(NN * 128 + 255) / 256, 256>>>(feat);

    // layer 1: 512 -> 256, relu
    k_pgemm<128><<<dim3(2, mTiles), 256, SM128>>>(Ah, Al, Bh + WOFF0, Bl + WOFF0, Y, NN, 512, 256);
    k_agg<256, true, false, true><<<(NN + 3) / 4, 256>>>(Y, b0, nullptr, Ah, Al);

    // layer 2: 256 -> 256, relu
    k_pgemm<128><<<dim3(2, mTiles), 256, SM128>>>(Ah, Al, Bh + WOFF1, Bl + WOFF1, Y, NN, 256, 256);
    k_agg<256, true, false, true><<<(NN + 3) / 4, 256>>>(Y, b1, nullptr, Ah, Al);

    // layer 3: 256 -> 128, no act -> aspect_embed (fp32) + split for layer 4
    k_pgemm<128><<<dim3(1, mTiles), 256, SM128>>>(Ah, Al, Bh + WOFF2, Bl + WOFF2, Y, NN, 256, 128);
    k_agg<128, false, true, true><<<(NN + 7) / 8, 256>>>(Y, b2, aspect, Ah, Al);

    // layer 4: 128 -> 64, no act -> final h
    k_pgemm<64><<<dim3(1, mTiles), 128, SM64>>>(Ah, Al, Bh + WOFF3, Bl + WOFF3, Y, NN, 128, 64);
    k_agg<64, false, true, false><<<(NN + 15) / 16, 256>>>(Y, b3, final_, nullptr, nullptr);
}

// round 16
// speedup vs baseline: 1.1070x; 1.1070x over previous
#include <cuda_runtime.h>
#include <cuda_bf16.h>
#include <cstdint>

#define NN 50000
#define NE 800000
#define MAXD 256
#define NBLK 196   // ceil(NN/256)

// ---------------- scratch (device globals) ----------------
__device__ int   g_deg_in[NN];
__device__ int   g_deg_out[NN];
__device__ int   g_cnt[NN];
__device__ float g_norm_s[NN];
__device__ float g_norm_d[NN];
__device__ int   g_off[NN + 1];
__device__ int   g_bsum[NBLK];
__device__ int   g_csr[NE];
__device__ float g_Y[(size_t)NN * MAXD];

// pre-split GEMM A operand (h * norm_s), bf16 hi/lo
__device__ __nv_bfloat16 g_Ah[(size_t)NN * 512];
__device__ __nv_bfloat16 g_Al[(size_t)NN * 512];

// pre-converted weights, transposed to [N][K], bf16 hi/lo split
#define WOFF0 0
#define WOFF1 131072
#define WOFF2 196608
#define WOFF3 229376
#define WTOT  237568
__device__ __nv_bfloat16 g_Bh[WTOT];
__device__ __nv_bfloat16 g_Bl[WTOT];

// ---------------- helpers ----------------
__device__ __forceinline__ uint32_t smem_to_u32(const void* p) {
    uint32_t a;
    asm("{ .reg .u64 t; cvta.to.shared.u64 t, %1; cvt.u32.u64 %0, t; }" : "=r"(a) : "l"(p));
    return a;
}
__device__ __forceinline__ void cp16(uint32_t dst, const void* src, int sz) {
    asm volatile("cp.async.cg.shared.global [%0], [%1], 16, %2;" :: "r"(dst), "l"(src), "r"(sz));
}
#define CP_COMMIT() asm volatile("cp.async.commit_group;" ::: "memory")
#define CP_WAIT(n)  asm volatile("cp.async.wait_group %0;" :: "n"(n) : "memory")

__device__ __forceinline__ void mma16816(float& c0, float& c1, float& c2, float& c3,
                                         uint32_t a0, uint32_t a1, uint32_t a2, uint32_t a3,
                                         uint32_t b0, uint32_t b1) {
    asm volatile(
        "mma.sync.aligned.m16n8k16.row.col.f32.bf16.bf16.f32 "
        "{%0,%1,%2,%3}, {%4,%5,%6,%7}, {%8,%9}, {%0,%1,%2,%3};"
        : "+f"(c0), "+f"(c1), "+f"(c2), "+f"(c3)
        : "r"(a0), "r"(a1), "r"(a2), "r"(a3), "r"(b0), "r"(b1));
}

__device__ __forceinline__ void ldsm4(uint32_t& r0, uint32_t& r1, uint32_t& r2, uint32_t& r3,
                                      uint32_t addr) {
    asm volatile("ldmatrix.sync.aligned.m8n8.x4.shared.b16 {%0,%1,%2,%3}, [%4];"
                 : "=r"(r0), "=r"(r1), "=r"(r2), "=r"(r3) : "r"(addr));
}

__device__ __forceinline__ void split2(float x0, float x1, uint32_t& hi, uint32_t& lo) {
    __nv_bfloat16 h0 = __float2bfloat16(x0), h1 = __float2bfloat16(x1);
    __nv_bfloat162 hp; hp.x = h0; hp.y = h1;
    __nv_bfloat162 lp = __floats2bfloat162_rn(x0 - __bfloat162float(h0),
                                              x1 - __bfloat162float(h1));
    hi = *reinterpret_cast<uint32_t*>(&hp);
    lo = *reinterpret_cast<uint32_t*>(&lp);
}

// ---------------- graph preprocessing ----------------
__global__ void k_zero() {
    int i = blockIdx.x * blockDim.x + threadIdx.x;
    if (i < NN) { g_deg_in[i] = 0; g_deg_out[i] = 0; g_cnt[i] = 0; }
}

__global__ void k_deg(const int* __restrict__ src, const int* __restrict__ dst) {
    int i = blockIdx.x * blockDim.x + threadIdx.x;
    if (i < NE) {
        atomicAdd(&g_deg_out[src[i]], 1);
        atomicAdd(&g_deg_in[dst[i]], 1);
    }
}

// scan phase 1 + norm computation fused (reads both degree arrays anyway)
__global__ __launch_bounds__(256) void k_scan1() {
    __shared__ int wsum[8];
    int i = blockIdx.x * 256 + threadIdx.x;
    int v = 0;
    if (i < NN) {
        v = g_deg_in[i];
        int doo = g_deg_out[i]; if (doo < 1) doo = 1;
        int dii = v;            if (dii < 1) dii = 1;
        g_norm_s[i] = rsqrtf((float)doo);
        g_norm_d[i] = rsqrtf((float)dii);
    }
    int s = v;
#pragma unroll
    for (int d = 16; d > 0; d >>= 1) s += __shfl_down_sync(0xffffffffu, s, d);
    int lane = threadIdx.x & 31, wid = threadIdx.x >> 5;
    if (lane == 0) wsum[wid] = s;
    __syncthreads();
    if (threadIdx.x < 8) {
        int t = wsum[threadIdx.x];
#pragma unroll
        for (int d = 4; d > 0; d >>= 1) t += __shfl_down_sync(0xffu, t, d);
        if (threadIdx.x == 0) g_bsum[blockIdx.x] = t;
    }
}

__global__ __launch_bounds__(256) void k_scan2() {
    __shared__ int wsc[8];
    int t = threadIdx.x;
    int v = (t < NBLK) ? g_bsum[t] : 0;
    int lane = t & 31, wid = t >> 5;
    int inc = v;
#pragma unroll
    for (int d = 1; d < 32; d <<= 1) {
        int u = __shfl_up_sync(0xffffffffu, inc, d);
        if (lane >= d) inc += u;
    }
    if (lane == 31) wsc[wid] = inc;
    __syncthreads();
    if (t < 8) {
        int s = wsc[t];
        int si = s;
#pragma unroll
        for (int d = 1; d < 8; d <<= 1) {
            int u = __shfl_up_sync(0xffu, si, d);
            if (t >= d) si += u;
        }
        wsc[t] = si - s;
        if (t == 7) g_off[NN] = si;
    }
    __syncthreads();
    int excl = inc - v + wsc[wid];
    if (t < NBLK) g_bsum[t] = excl;
}

__global__ __launch_bounds__(256) void k_scan3() {
    __shared__ int wsc[8];
    int i = blockIdx.x * 256 + threadIdx.x;
    int v = (i < NN) ? g_deg_in[i] : 0;
    int lane = threadIdx.x & 31, wid = threadIdx.x >> 5;
    int inc = v;
#pragma unroll
    for (int d = 1; d < 32; d <<= 1) {
        int u = __shfl_up_sync(0xffffffffu, inc, d);
        if (lane >= d) inc += u;
    }
    if (lane == 31) wsc[wid] = inc;
    __syncthreads();
    if (threadIdx.x < 8) {
        int s = wsc[threadIdx.x];
        int si = s;
#pragma unroll
        for (int d = 1; d < 8; d <<= 1) {
            int u = __shfl_up_sync(0xffu, si, d);
            if (threadIdx.x >= d) si += u;
        }
        wsc[threadIdx.x] = si - s;
    }
    __syncthreads();
    int excl = inc - v + wsc[wid] + g_bsum[blockIdx.x];
    if (i < NN) g_off[i] = excl;
}

__global__ void k_fill(const int* __restrict__ src, const int* __restrict__ dst) {
    int i = blockIdx.x * blockDim.x + threadIdx.x;
    if (i < NE) {
        int d = dst[i];
        int p = atomicAdd(&g_cnt[d], 1);
        g_csr[g_off[d] + p] = src[i];
    }
}

// ---------------- fused weight pre-conversion: all four W -> Bh/Bl [N][K] bf16 ----------------
__global__ __launch_bounds__(256) void k_wconv_all(const float* __restrict__ W0,
                                                   const float* __restrict__ W1,
                                                   const float* __restrict__ W2,
                                                   const float* __restrict__ W3) {
    int idx = blockIdx.x * blockDim.x + threadIdx.x;
    if (idx >= WTOT) return;
    const float* W; int K, N, local, off;
    if (idx < WOFF1)      { W = W0; K = 512; N = 256; off = WOFF0; local = idx; }
    else if (idx < WOFF2) { W = W1; K = 256; N = 256; off = WOFF1; local = idx - WOFF1; }
    else if (idx < WOFF3) { W = W2; K = 256; N = 128; off = WOFF2; local = idx - WOFF2; }
    else                  { W = W3; K = 128; N = 64;  off = WOFF3; local = idx - WOFF3; }
    int k = local / N, n = local % N;
    float x = W[local];
    __nv_bfloat16 h = __float2bfloat16(x);
    float lo = x - __bfloat162float(h);
    g_Bh[off + n * K + k] = h;
    g_Bl[off + n * K + k] = __float2bfloat16(lo);
}

// ---------------- feature pre-split ----------------
__global__ __launch_bounds__(256) void k_sfeat(const float* __restrict__ feat) {
    int idx = blockIdx.x * 256 + threadIdx.x;
    if (idx >= NN * 128) return;
    int node = idx >> 7;
    float ns = g_norm_s[node];
    float4 a = ((const float4*)feat)[idx];
    uint32_t h0, l0, h1, l1;
    split2(a.x * ns, a.y * ns, h0, l0);
    split2(a.z * ns, a.w * ns, h1, l1);
    ((uint2*)g_Ah)[idx] = make_uint2(h0, h1);
    ((uint2*)g_Al)[idx] = make_uint2(l0, l1);
}

// ---------------- cp.async stage issue ----------------
template <int BN, int THREADS>
__device__ __forceinline__ void issue_stage(
    uint32_t sb,
    const __nv_bfloat16* __restrict__ Ah, const __nv_bfloat16* __restrict__ Al,
    const __nv_bfloat16* __restrict__ Bh, const __nv_bfloat16* __restrict__ Bl,
    int tid, int mTile, int nTile, int k0, int M, int K) {
    const int A_BYTES = 128 * 40 * 2;
    const int B_BYTES = BN * 40 * 2;
#pragma unroll
    for (int it = 0; it < 512 / THREADS; it++) {
        int c = tid + it * THREADS;
        int row = c >> 2, seg = c & 3;
        int gm = mTile + row;
        int sz = (gm < M) ? 16 : 0;
        int gms = (gm < M) ? gm : (M - 1);
        size_t goff = (size_t)gms * K + k0 + seg * 8;
        uint32_t d = sb + row * 80 + seg * 16;
        cp16(d, Ah + goff, sz);
        cp16(d + A_BYTES, Al + goff, sz);
    }
#pragma unroll
    for (int it = 0; it < (BN * 4) / THREADS; it++) {
        int c = tid + it * THREADS;
        int row = c >> 2, seg = c & 3;
        size_t goff = (size_t)(nTile + row) * K + k0 + seg * 8;
        uint32_t d = sb + 2 * A_BYTES + row * 80 + seg * 16;
        cp16(d, Bh + goff, 16);
        cp16(d + B_BYTES, Bl + goff, 16);
    }
}

// ---------------- pipelined tensor-core GEMM (3-term bf16 split, ldmatrix frags) ----------------
template <int BN>
__global__ __launch_bounds__(2 * (BN / 32) * 32, 2)
void k_pgemm(const __nv_bfloat16* __restrict__ Ah, const __nv_bfloat16* __restrict__ Al,
             const __nv_bfloat16* __restrict__ Bh, const __nv_bfloat16* __restrict__ Bl,
             float* __restrict__ Y, int M, int K, int Nstride) {
    const int THREADS = 2 * (BN / 32) * 32;
    const int ST = 40;
    const int A_BYTES = 128 * ST * 2;
    const int B_BYTES = BN * ST * 2;
    const int STAGE = 2 * A_BYTES + 2 * B_BYTES;
    extern __shared__ char smem[];
    uint32_t sbase = smem_to_u32(smem);

    int tid = threadIdx.x;
    int wid = tid >> 5;
    int lane = tid & 31;
    int grp = lane >> 2;
    int qid = lane & 3;
    int mbase = (wid & 1) * 64;
    int nbase = (wid >> 1) * 32;
    int mTile = blockIdx.y * 128;
    int nTile = blockIdx.x * BN;
    int nchunk = K >> 5;

    // per-thread ldmatrix byte offsets
    uint32_t aoff = (uint32_t)(mbase + ((lane >> 3) & 1) * 8 + (lane & 7)) * 80
                  + ((lane >> 4) & 1) * 16;
    uint32_t boff = (uint32_t)(nbase + ((lane >> 4) & 1) * 8 + (lane & 7)) * 80
                  + ((lane >> 3) & 1) * 16;

    float acc[4][4][4];
#pragma unroll
    for (int i = 0; i < 4; i++)
#pragma unroll
        for (int j = 0; j < 4; j++)
#pragma unroll
            for (int r = 0; r < 4; r++) acc[i][j][r] = 0.f;

    issue_stage<BN, THREADS>(sbase, Ah, Al, Bh, Bl, tid, mTile, nTile, 0, M, K);
    CP_COMMIT();

    for (int c = 0; c < nchunk; c++) {
        if (c + 1 < nchunk) {
            issue_stage<BN, THREADS>(sbase + ((c + 1) & 1) * STAGE, Ah, Al, Bh, Bl,
                                     tid, mTile, nTile, (c + 1) * 32, M, K);
            CP_COMMIT();
            CP_WAIT(1);
        } else {
            CP_WAIT(0);
        }
        __syncthreads();

        uint32_t stA = sbase + (c & 1) * STAGE;           // A_hi
        uint32_t stB = stA + 2 * A_BYTES;                 // B_hi

#pragma unroll
        for (int ks = 0; ks < 2; ks++) {
            uint32_t kby = (uint32_t)(ks * 32);           // k16 step -> 32 bytes

            uint32_t bh[4][2], bl[4][2];
#pragma unroll
            for (int p = 0; p < 2; p++) {
                uint32_t ba = stB + boff + p * 16 * 80 + kby;
                ldsm4(bh[2 * p][0], bh[2 * p][1], bh[2 * p + 1][0], bh[2 * p + 1][1], ba);
                ldsm4(bl[2 * p][0], bl[2 * p][1], bl[2 * p + 1][0], bl[2 * p + 1][1],
                      ba + B_BYTES);
            }

#pragma unroll
            for (int mt = 0; mt < 4; mt++) {
                uint32_t aa = stA + aoff + mt * 16 * 80 + kby;
                uint32_t ah0, ah1, ah2, ah3, al0, al1, al2, al3;
                ldsm4(ah0, ah1, ah2, ah3, aa);
                ldsm4(al0, al1, al2, al3, aa + A_BYTES);
#pragma unroll
                for (int nt = 0; nt < 4; nt++) {
                    mma16816(acc[mt][nt][0], acc[mt][nt][1], acc[mt][nt][2], acc[mt][nt][3],
                             ah0, ah1, ah2, ah3, bh[nt][0], bh[nt][1]);
                    mma16816(acc[mt][nt][0], acc[mt][nt][1], acc[mt][nt][2], acc[mt][nt][3],
                             ah0, ah1, ah2, ah3, bl[nt][0], bl[nt][1]);
                    mma16816(acc[mt][nt][0], acc[mt][nt][1], acc[mt][nt][2], acc[mt][nt][3],
                             al0, al1, al2, al3, bh[nt][0], bh[nt][1]);
                }
            }
        }
        __syncthreads();
    }

    // epilogue
#pragma unroll
    for (int mt = 0; mt < 4; mt++) {
        int r0 = mTile + mbase + mt * 16 + grp;
        int r1 = r0 + 8;
#pragma unroll
        for (int nt = 0; nt < 4; nt++) {
            int col = nTile + nbase + nt * 8 + qid * 2;
            if (r0 < M) {
                float2 v = make_float2(acc[mt][nt][0], acc[mt][nt][1]);
                *(float2*)(Y + (size_t)r0 * Nstride + col) = v;
            }
            if (r1 < M) {
                float2 v = make_float2(acc[mt][nt][2], acc[mt][nt][3]);
                *(float2*)(Y + (size_t)r1 * Nstride + col) = v;
            }
        }
    }
}

// ---------------- aggregation (optionally emits next layer's split A operand) ----------------
template <int DIM, bool RELU, bool WF32, bool WSPLIT>
__global__ __launch_bounds__(256) void k_agg(const float* __restrict__ Y,
                                             const float* __restrict__ b,
                                             float* __restrict__ outF,
                                             __nv_bfloat16* __restrict__ outH,
                                             __nv_bfloat16* __restrict__ outL) {
    const int VPT = DIM / 4;
    const int G = 256 / VPT;
    int t = threadIdx.x;
    int node = blockIdx.x * G + t / VPT;
    int lane = t % VPT;
    if (node >= NN) return;

    int p0 = g_off[node];
    int p1 = g_off[node + 1];
    const float4* Yv = (const float4*)Y;

    float4 acc0 = make_float4(0.f, 0.f, 0.f, 0.f);
    float4 acc1 = make_float4(0.f, 0.f, 0.f, 0.f);
    int p = p0;
    for (; p + 1 < p1; p += 2) {
        int s0 = g_csr[p];
        int s1 = g_csr[p + 1];
        float4 v0 = Yv[(size_t)s0 * VPT + lane];
        float4 v1 = Yv[(size_t)s1 * VPT + lane];
        acc0.x += v0.x; acc0.y += v0.y; acc0.z += v0.z; acc0.w += v0.w;
        acc1.x += v1.x; acc1.y += v1.y; acc1.z += v1.z; acc1.w += v1.w;
    }
    if (p < p1) {
        int s0 = g_csr[p];
        float4 v0 = Yv[(size_t)s0 * VPT + lane];
        acc0.x += v0.x; acc0.y += v0.y; acc0.z += v0.z; acc0.w += v0.w;
    }

    float nd = g_norm_d[node];
    float4 bb = ((const float4*)b)[lane];
    float4 r;
    r.x = (acc0.x + acc1.x) * nd + bb.x;
    r.y = (acc0.y + acc1.y) * nd + bb.y;
    r.z = (acc0.z + acc1.z) * nd + bb.z;
    r.w = (acc0.w + acc1.w) * nd + bb.w;
    if (RELU) {
        r.x = fmaxf(r.x, 0.f); r.y = fmaxf(r.y, 0.f);
        r.z = fmaxf(r.z, 0.f); r.w = fmaxf(r.w, 0.f);
    }
    size_t oidx = (size_t)node * VPT + lane;
    if (WF32) ((float4*)outF)[oidx] = r;
    if (WSPLIT) {
        float ns = g_norm_s[node];
        uint32_t h0, l0, h1, l1;
        split2(r.x * ns, r.y * ns, h0, l0);
        split2(r.z * ns, r.w * ns, h1, l1);
        ((uint2*)outH)[oidx] = make_uint2(h0, h1);
        ((uint2*)outL)[oidx] = make_uint2(l0, l1);
    }
}

// ---------------- launch ----------------
extern "C" void kernel_launch(void* const* d_in, const int* in_sizes, int n_in,
                              void* d_out, int out_size) {
    const float* feat = (const float*)d_in[0];
    const int*   src  = (const int*)d_in[1];
    const int*   dst  = (const int*)d_in[2];
    const float* W0 = (const float*)d_in[3];
    const float* b0 = (const float*)d_in[4];
    const float* W1 = (const float*)d_in[5];
    const float* b1 = (const float*)d_in[6];
    const float* W2 = (const float*)d_in[7];
    const float* b2 = (const float*)d_in[8];
    const float* W3 = (const float*)d_in[9];
    const float* b3 = (const float*)d_in[10];

    float* out    = (float*)d_out;
    float* aspect = out;                          // NN x 128
    float* final_ = out + (size_t)NN * 128;       // NN x 64

    void* p;
    cudaGetSymbolAddress(&p, g_Y);  float* Y = (float*)p;
    cudaGetSymbolAddress(&p, g_Ah); __nv_bfloat16* Ah = (__nv_bfloat16*)p;
    cudaGetSymbolAddress(&p, g_Al); __nv_bfloat16* Al = (__nv_bfloat16*)p;
    cudaGetSymbolAddress(&p, g_Bh); __nv_bfloat16* Bh = (__nv_bfloat16*)p;
    cudaGetSymbolAddress(&p, g_Bl); __nv_bfloat16* Bl = (__nv_bfloat16*)p;

    const int SM128 = 2 * (2 * 128 * 40 * 2 + 2 * 128 * 40 * 2);  // 81920
    const int SM64  = 2 * (2 * 128 * 40 * 2 + 2 * 64 * 40 * 2);   // 61440
    cudaFuncSetAttribute(k_pgemm<128>, cudaFuncAttributeMaxDynamicSharedMemorySize, SM128);
    cudaFuncSetAttribute(k_pgemm<64>,  cudaFuncAttributeMaxDynamicSharedMemorySize, SM64);

    const int TB = 256;
    int nodeBlocks = (NN + TB - 1) / TB;
    int edgeBlocks = (NE + TB - 1) / TB;
    int mTiles = (NN + 127) / 128;               // 391

    // preprocessing (norm fused into scan1; 4 wconv fused into 1)
    k_zero<<<nodeBlocks, TB>>>();
    k_deg<<<edgeBlocks, TB>>>(src, dst);
    k_scan1<<<NBLK, TB>>>();
    k_scan2<<<1, TB>>>();
    k_scan3<<<NBLK, TB>>>();
    k_fill<<<edgeBlocks, TB>>>(src, dst);

    k_wconv_all<<<(WTOT + 255) / 256, 256>>>(W0, W1, W2, W3);
    k_sfeat<<<(NN * 128 + 255) / 256, 256>>>(feat);

    // layer 1: 512 -> 256, relu
    k_pgemm<128><<<dim3(2, mTiles), 256, SM128>>>(Ah, Al, Bh + WOFF0, Bl + WOFF0, Y, NN, 512, 256);
    k_agg<256, true, false, true><<<(NN + 3) / 4, 256>>>(Y, b0, nullptr, Ah, Al);

    // layer 2: 256 -> 256, relu
    k_pgemm<128><<<dim3(2, mTiles), 256, SM128>>>(Ah, Al, Bh + WOFF1, Bl + WOFF1, Y, NN, 256, 256);
    k_agg<256, true, false, true><<<(NN + 3) / 4, 256>>>(Y, b1, nullptr, Ah, Al);

    // layer 3: 256 -> 128, no act -> aspect_embed (fp32) + split for layer 4
    k_pgemm<128><<<dim3(1, mTiles), 256, SM128>>>(Ah, Al, Bh + WOFF2, Bl + WOFF2, Y, NN, 256, 128);
    k_agg<128, false, true, true><<<(NN + 7) / 8, 256>>>(Y, b2, aspect, Ah, Al);

    // layer 4: 128 -> 64, no act -> final h
    k_pgemm<64><<<dim3(1, mTiles), 128, SM64>>>(Ah, Al, Bh + WOFF3, Bl + WOFF3, Y, NN, 128, 64);
    k_agg<64, false, true, false><<<(NN + 15) / 16, 256>>>(Y, b3, final_, nullptr, nullptr);
}